// round 8
// baseline (speedup 1.0000x reference)
#include <cuda_runtime.h>
#include <cuda_fp16.h>

// IVPLoss: 8-step Euler trajectories of bilinear-sampled vector fields,
// MSE between pred and true trajectories (incl. identity step 0).
//
// R8 = R7 traj (bottom-row pad; traj ~88us) + SMEM-staged repack:
//  - one block per (row,batch); stage the 4 input rows (2 fields x 2
//    channels, 768 floats each) in SMEM via coalesced float4 loads —
//    every input float read exactly ONCE from global, x+1 neighbor
//    comes from SMEM;
//  - emit 3 lane-coalesced uint2 elements/thread from SMEM.
//
// Packed layout per pixel (8B): { half2(c0[x],c1[x]), half2(c0[x+1],c1[x+1]) }
// -> one bilinear sample = 2 coalesced LDG.64 + HFMA2 lerps.

#define Bv 8
#define Hv 768
#define Wv 768
#define WPK 769                      // padded width  (col 768 = col 767)
#define HPK 769                      // padded height (row 768 = row 767)
#define NSTEPS 8
#define DXC 0.5f

#define PLANE (Hv * Wv)              // 589824
#define PK_PLANE (HPK * WPK)         // 591361
#define PK_TOTAL (Bv * PK_PLANE)

__device__ uint2 g_pred[PK_TOTAL];
__device__ uint2 g_true[PK_TOTAL];
__device__ double g_acc;

__device__ __forceinline__ unsigned int h2u(__half2 h) {
    return *reinterpret_cast<unsigned int*>(&h);
}

// grid (HPK, Bv), block 256: one block per padded output row.
__global__ __launch_bounds__(256) void repack_kernel(const float* __restrict__ pred,
                                                     const float* __restrict__ tru) {
    __shared__ float s[4][Wv];       // [0]=pred c0, [1]=pred c1, [2]=true c0, [3]=true c1

    int y = blockIdx.x;              // 0..768 (row 768 duplicates 767)
    int b = blockIdx.y;
    int tx = threadIdx.x;
    if (y == 0 && b == 0 && tx == 0) g_acc = 0.0;

    int ys = min(y, Hv - 1);
    int rbase = b * 2 * PLANE + ys * Wv;         // channel-0 input row base

    // stage: 4 arrays x 192 float4 each; threads 0..191 active per array
    const float* srcs[4] = { pred + rbase, pred + rbase + PLANE,
                             tru  + rbase, tru  + rbase + PLANE };
    if (tx < 192) {
        #pragma unroll
        for (int a = 0; a < 4; a++) {
            float4 v = __ldcs(reinterpret_cast<const float4*>(srcs[a]) + tx);
            *reinterpret_cast<float4*>(&s[a][tx * 4]) = v;
        }
    }
    __syncthreads();

    int obase = b * PK_PLANE + y * WPK;          // packed output row base

    #pragma unroll
    for (int k = 0; k < 3; k++) {
        int x = tx + k * 256;                    // 0..767, lane-coalesced
        int x1 = min(x + 1, Wv - 1);
        __half2 pp0 = __floats2half2_rn(s[0][x],  s[1][x]);
        __half2 pp1 = __floats2half2_rn(s[0][x1], s[1][x1]);
        __half2 tp0 = __floats2half2_rn(s[2][x],  s[3][x]);
        __half2 tp1 = __floats2half2_rn(s[2][x1], s[3][x1]);
        g_pred[obase + x] = make_uint2(h2u(pp0), h2u(pp1));
        g_true[obase + x] = make_uint2(h2u(tp0), h2u(tp1));
    }
    if (tx == 0) {                               // pad col 768 = dup of 767
        __half2 pe = __floats2half2_rn(s[0][Wv - 1], s[1][Wv - 1]);
        __half2 te = __floats2half2_rn(s[2][Wv - 1], s[3][Wv - 1]);
        g_pred[obase + Wv] = make_uint2(h2u(pe), h2u(pe));
        g_true[obase + Wv] = make_uint2(h2u(te), h2u(te));
    }
}

__device__ __forceinline__ float2 bsample(const uint2* __restrict__ P,
                                          float x, float y) {
    // clip to [0, W-1] / [0, H-1] (matches jnp.clip)
    x = fminf(fmaxf(x, 0.0f), (float)(Wv - 1));
    y = fminf(fmaxf(y, 0.0f), (float)(Hv - 1));
    float xf = floorf(x);
    float yf = floorf(y);
    int xi = (int)xf;
    int yi = (int)yf;
    __half2 wx2 = __float2half2_rn(x - xf);
    __half2 wy2 = __float2half2_rn(y - yf);

    int ofs = yi * WPK + xi;
    uint2 r0 = __ldg(P + ofs);
    uint2 r1 = __ldg(P + ofs + WPK);    // padded bottom row: always valid
    __half2 v00 = *reinterpret_cast<__half2*>(&r0.x);
    __half2 v01 = *reinterpret_cast<__half2*>(&r0.y);
    __half2 v10 = *reinterpret_cast<__half2*>(&r1.x);
    __half2 v11 = *reinterpret_cast<__half2*>(&r1.y);

    __half2 top = __hfma2(wx2, __hsub2(v01, v00), v00);
    __half2 bot = __hfma2(wx2, __hsub2(v11, v10), v10);
    __half2 res = __hfma2(wy2, __hsub2(bot, top), top);
    return __half22float2(res);
}

__global__ __launch_bounds__(256) void traj_kernel() {
    int x = blockIdx.x * blockDim.x + threadIdx.x;  // 0..767
    int y = blockIdx.y;
    int b = blockIdx.z;
    const uint2* __restrict__ Pp = g_pred + b * PK_PLANE;
    const uint2* __restrict__ Pt = g_true + b * PK_PLANE;

    float pxp = (float)x, pyp = (float)y;   // pred trajectory
    float pxt = (float)x, pyt = (float)y;   // true trajectory
    float acc = 0.0f;

    #pragma unroll
    for (int s = 0; s < NSTEPS; s++) {
        float2 vp = bsample(Pp, pxp, pyp);
        float2 vt = bsample(Pt, pxt, pyt);
        pxp = fmaf(DXC, vp.x, pxp);
        pyp = fmaf(DXC, vp.y, pyp);
        pxt = fmaf(DXC, vt.x, pxt);
        pyt = fmaf(DXC, vt.y, pyt);
        float dx = pxt - pxp;
        float dy = pyt - pyp;
        acc = fmaf(dx, dx, acc);
        acc = fmaf(dy, dy, acc);
    }

    // block reduction: warp shuffle -> shared -> warp0 -> atomicAdd(double)
    float v = acc;
    #pragma unroll
    for (int o = 16; o > 0; o >>= 1)
        v += __shfl_down_sync(0xffffffffu, v, o);

    __shared__ float sred[8];
    int lane = threadIdx.x & 31;
    int wid  = threadIdx.x >> 5;
    if (lane == 0) sred[wid] = v;
    __syncthreads();
    if (wid == 0) {
        v = (lane < 8) ? sred[lane] : 0.0f;
        #pragma unroll
        for (int o = 4; o > 0; o >>= 1)
            v += __shfl_down_sync(0xffffffffu, v, o);
        if (lane == 0) atomicAdd(&g_acc, (double)v);
    }
}

__global__ void finalize_kernel(float* __restrict__ out) {
    const double cnt = (double)(NSTEPS + 1) * Bv * 2 * Hv * Wv;  // 84934656
    *out = (float)(g_acc / cnt);
}

extern "C" void kernel_launch(void* const* d_in, const int* in_sizes, int n_in,
                              void* d_out, int out_size) {
    const float* vf_pred = (const float*)d_in[0];
    const float* vf_true = (const float*)d_in[1];
    float* out = (float*)d_out;

    dim3 rp_grid(HPK, Bv);
    repack_kernel<<<rp_grid, 256>>>(vf_pred, vf_true);

    dim3 grid(Wv / 256, Hv, Bv);
    traj_kernel<<<grid, 256>>>();

    finalize_kernel<<<1, 1>>>(out);
}

// round 9
// speedup vs baseline: 1.5110x; 1.5110x over previous
#include <cuda_runtime.h>
#include <cuda_fp16.h>

// IVPLoss: 8-step Euler trajectories of bilinear-sampled vector fields,
// MSE between pred and true trajectories (incl. identity step 0).
//
// R9 = best measured components, recombined:
//  - repack: R2's per-pixel gather (24.5us measured — beats every
//    "improved" variant tried in R4/R7/R8), extended to write the
//    duplicated bottom row (row 768 = row 767).
//  - traj: R7 body — fp16 dup-pair element + padded bottom row, so one
//    bilinear sample = 2 coalesced LDG.64 + HFMA2 lerps, no y+1 clamp.
//  - separate tiny finalize kernel (fused epilogues regressed in R3).
//
// Packed layout per pixel (8B): { half2(c0[x],c1[x]), half2(c0[x+1],c1[x+1]) }

#define Bv 8
#define Hv 768
#define Wv 768
#define WPK 769                      // padded width  (col 768 = col 767)
#define HPK 769                      // padded height (row 768 = row 767)
#define NSTEPS 8
#define DXC 0.5f

#define PLANE (Hv * Wv)              // 589824
#define PK_PLANE (HPK * WPK)         // 591361
#define PK_TOTAL (Bv * PK_PLANE)     // 4730888

__device__ uint2 g_pred[PK_TOTAL];
__device__ uint2 g_true[PK_TOTAL];
__device__ double g_acc;

__device__ __forceinline__ unsigned int h2u(__half2 h) {
    return *reinterpret_cast<unsigned int*>(&h);
}

__device__ __forceinline__ uint2 pack_pair(const float* __restrict__ f,
                                           int base, int xs, int x1) {
    __half2 p0 = __floats2half2_rn(__ldg(f + base + xs),
                                   __ldg(f + base + PLANE + xs));
    __half2 p1 = __floats2half2_rn(__ldg(f + base + x1),
                                   __ldg(f + base + PLANE + x1));
    return make_uint2(h2u(p0), h2u(p1));
}

// one thread per packed element (R2 structure; best measured repack)
__global__ __launch_bounds__(256) void repack_kernel(const float* __restrict__ pred,
                                                     const float* __restrict__ tru) {
    int idx = blockIdx.x * blockDim.x + threadIdx.x;
    if (idx == 0) g_acc = 0.0;
    if (idx >= PK_TOTAL) return;
    int x = idx % WPK;
    int rest = idx / WPK;
    int y = rest % HPK;
    int b = rest / HPK;
    int xs = min(x, Wv - 1);                 // padded col duplicates last col
    int x1 = min(xs + 1, Wv - 1);
    int ys = min(y, Hv - 1);                 // padded row duplicates last row
    int base = b * 2 * PLANE + ys * Wv;      // channel-0 row base
    g_pred[idx] = pack_pair(pred, base, xs, x1);
    g_true[idx] = pack_pair(tru,  base, xs, x1);
}

__device__ __forceinline__ float2 bsample(const uint2* __restrict__ P,
                                          float x, float y) {
    // clip to [0, W-1] / [0, H-1] (matches jnp.clip)
    x = fminf(fmaxf(x, 0.0f), (float)(Wv - 1));
    y = fminf(fmaxf(y, 0.0f), (float)(Hv - 1));
    float xf = floorf(x);
    float yf = floorf(y);
    int xi = (int)xf;
    int yi = (int)yf;
    __half2 wx2 = __float2half2_rn(x - xf);
    __half2 wy2 = __float2half2_rn(y - yf);

    int ofs = yi * WPK + xi;
    uint2 r0 = __ldg(P + ofs);
    uint2 r1 = __ldg(P + ofs + WPK);    // padded bottom row: always valid
    __half2 v00 = *reinterpret_cast<__half2*>(&r0.x);
    __half2 v01 = *reinterpret_cast<__half2*>(&r0.y);
    __half2 v10 = *reinterpret_cast<__half2*>(&r1.x);
    __half2 v11 = *reinterpret_cast<__half2*>(&r1.y);

    __half2 top = __hfma2(wx2, __hsub2(v01, v00), v00);
    __half2 bot = __hfma2(wx2, __hsub2(v11, v10), v10);
    __half2 res = __hfma2(wy2, __hsub2(bot, top), top);
    return __half22float2(res);
}

__global__ __launch_bounds__(256) void traj_kernel() {
    int x = blockIdx.x * blockDim.x + threadIdx.x;  // 0..767
    int y = blockIdx.y;
    int b = blockIdx.z;
    const uint2* __restrict__ Pp = g_pred + b * PK_PLANE;
    const uint2* __restrict__ Pt = g_true + b * PK_PLANE;

    float pxp = (float)x, pyp = (float)y;   // pred trajectory
    float pxt = (float)x, pyt = (float)y;   // true trajectory
    float acc = 0.0f;

    #pragma unroll
    for (int s = 0; s < NSTEPS; s++) {
        float2 vp = bsample(Pp, pxp, pyp);
        float2 vt = bsample(Pt, pxt, pyt);
        pxp = fmaf(DXC, vp.x, pxp);
        pyp = fmaf(DXC, vp.y, pyp);
        pxt = fmaf(DXC, vt.x, pxt);
        pyt = fmaf(DXC, vt.y, pyt);
        float dx = pxt - pxp;
        float dy = pyt - pyp;
        acc = fmaf(dx, dx, acc);
        acc = fmaf(dy, dy, acc);
    }

    // block reduction: warp shuffle -> shared -> warp0 -> atomicAdd(double)
    float v = acc;
    #pragma unroll
    for (int o = 16; o > 0; o >>= 1)
        v += __shfl_down_sync(0xffffffffu, v, o);

    __shared__ float sred[8];
    int lane = threadIdx.x & 31;
    int wid  = threadIdx.x >> 5;
    if (lane == 0) sred[wid] = v;
    __syncthreads();
    if (wid == 0) {
        v = (lane < 8) ? sred[lane] : 0.0f;
        #pragma unroll
        for (int o = 4; o > 0; o >>= 1)
            v += __shfl_down_sync(0xffffffffu, v, o);
        if (lane == 0) atomicAdd(&g_acc, (double)v);
    }
}

__global__ void finalize_kernel(float* __restrict__ out) {
    const double cnt = (double)(NSTEPS + 1) * Bv * 2 * Hv * Wv;  // 84934656
    *out = (float)(g_acc / cnt);
}

extern "C" void kernel_launch(void* const* d_in, const int* in_sizes, int n_in,
                              void* d_out, int out_size) {
    const float* vf_pred = (const float*)d_in[0];
    const float* vf_true = (const float*)d_in[1];
    float* out = (float*)d_out;

    int rp_blocks = (PK_TOTAL + 255) / 256;
    repack_kernel<<<rp_blocks, 256>>>(vf_pred, vf_true);

    dim3 grid(Wv / 256, Hv, Bv);
    traj_kernel<<<grid, 256>>>();

    finalize_kernel<<<1, 1>>>(out);
}